// round 1
// baseline (speedup 1.0000x reference)
#include <cuda_runtime.h>
#include <math.h>

#define BM 128
#define BN 128
#define BK 8
#define TM 8
#define TN 8

// ---------------- scratch (static device arrays; no allocations) -------------
__device__ float g_h1[4096UL * 1536];          // [B*S, 3D]        25 MB
__device__ float g_h2[4096UL * 12288];         // [B*S, 3D*H]     201 MB
__device__ float g_sc[16UL * 2048 * 2048];     // [B*H, S, S]     268 MB
__device__ float g_ap[4096UL * 4096];          // [B, S, H*D]      67 MB

// ---------------- generic tiled SGEMM: C = A @ op(B) (+bias) -----------------
// A: M x K row-major (lda). TRANSB: B is N x K row-major (ldb) -> C=A*B^T.
// !TRANSB: B is K x N row-major (ldb) -> C=A*B.
// Batched over blockIdx.z: z -> (h = z % NH, b = z / NH) with per-h / per-b strides.
template <bool TRANSB>
__global__ __launch_bounds__(256, 2)
void sgemm_kernel(const float* __restrict__ Ag, const float* __restrict__ Bg,
                  float* __restrict__ Cg, const float* __restrict__ bias,
                  int M, int N, int K, int lda, int ldb, int ldc,
                  int NH, size_t sAh, size_t sAb, size_t sBh, size_t sBb,
                  size_t sCh, size_t sCb)
{
    const int z  = blockIdx.z;
    const int hb = z % NH;
    const int bb = z / NH;
    const float* A = Ag + (size_t)hb * sAh + (size_t)bb * sAb;
    const float* B = Bg + (size_t)hb * sBh + (size_t)bb * sBb;
    float*       C = Cg + (size_t)hb * sCh + (size_t)bb * sCb;

    __shared__ float As[BK][BM];
    __shared__ float Bs[BK][BN];

    const int tid = threadIdx.x;
    const int bm = blockIdx.y * BM;
    const int bn = blockIdx.x * BN;

    // A tile load: 128 rows x 8 k; one float4 per thread
    const int arow = tid >> 1;
    const int acol = (tid & 1) << 2;
    // B tile load
    int brow, bcol;
    if (TRANSB) { brow = tid >> 1; bcol = (tid & 1) << 2; }   // 128 n-rows x 8 k
    else        { brow = tid >> 5; bcol = (tid & 31) << 2; }  // 8 k-rows x 128 n

    const int tx = tid & 15;   // 16 x 16 thread grid, 8x8 each
    const int ty = tid >> 4;

    const float* Aptr = A + (size_t)(bm + arow) * lda + acol;
    const float* Bptr = TRANSB ? (B + (size_t)(bn + brow) * ldb + bcol)
                               : (B + (size_t)brow * ldb + bn + bcol);

    float acc[TM][TN];
#pragma unroll
    for (int i = 0; i < TM; i++)
#pragma unroll
        for (int j = 0; j < TN; j++) acc[i][j] = 0.0f;

    // prefetch first tile into registers
    float4 av = *(const float4*)Aptr;
    float4 bv = *(const float4*)Bptr;

    for (int k0 = 0; k0 < K; k0 += BK) {
        As[acol + 0][arow] = av.x;
        As[acol + 1][arow] = av.y;
        As[acol + 2][arow] = av.z;
        As[acol + 3][arow] = av.w;
        if (TRANSB) {
            Bs[bcol + 0][brow] = bv.x;
            Bs[bcol + 1][brow] = bv.y;
            Bs[bcol + 2][brow] = bv.z;
            Bs[bcol + 3][brow] = bv.w;
        } else {
            *(float4*)&Bs[brow][bcol] = bv;
        }
        __syncthreads();

        // prefetch next tile (overlaps with FFMA issue below)
        if (k0 + BK < K) {
            Aptr += BK;
            Bptr += TRANSB ? (size_t)BK : (size_t)BK * ldb;
            av = *(const float4*)Aptr;
            bv = *(const float4*)Bptr;
        }

#pragma unroll
        for (int k = 0; k < BK; k++) {
            float a[TM], b[TN];
            *(float4*)&a[0] = *(const float4*)&As[k][ty * TM];
            *(float4*)&a[4] = *(const float4*)&As[k][ty * TM + 4];
            *(float4*)&b[0] = *(const float4*)&Bs[k][tx * TN];
            *(float4*)&b[4] = *(const float4*)&Bs[k][tx * TN + 4];
#pragma unroll
            for (int i = 0; i < TM; i++)
#pragma unroll
                for (int j = 0; j < TN; j++)
                    acc[i][j] = fmaf(a[i], b[j], acc[i][j]);
        }
        __syncthreads();
    }

    // epilogue: bias + store (vectorized)
    float bb8[TN];
#pragma unroll
    for (int j = 0; j < TN; j++)
        bb8[j] = bias ? bias[bn + tx * TN + j] : 0.0f;

#pragma unroll
    for (int i = 0; i < TM; i++) {
        float* crow = C + (size_t)(bm + ty * TM + i) * ldc + bn + tx * TN;
        float4 o0, o1;
        o0.x = acc[i][0] + bb8[0]; o0.y = acc[i][1] + bb8[1];
        o0.z = acc[i][2] + bb8[2]; o0.w = acc[i][3] + bb8[3];
        o1.x = acc[i][4] + bb8[4]; o1.y = acc[i][5] + bb8[5];
        o1.z = acc[i][6] + bb8[6]; o1.w = acc[i][7] + bb8[7];
        *(float4*)(crow)     = o0;
        *(float4*)(crow + 4) = o1;
    }
}

// ---------------- row softmax with pre-scale: p = softmax(scale * s) ---------
__global__ void softmax_rows(float* __restrict__ data, float scale)
{
    const int tid = threadIdx.x;
    float* p = data + (size_t)blockIdx.x * 2048;

    __shared__ float red[256];

    float v[8];
    float mx = -1e30f;
#pragma unroll
    for (int i = 0; i < 8; i++) {
        v[i] = p[tid + i * 256] * scale;
        mx = fmaxf(mx, v[i]);
    }
    red[tid] = mx;
    __syncthreads();
#pragma unroll
    for (int s = 128; s > 0; s >>= 1) {
        if (tid < s) red[tid] = fmaxf(red[tid], red[tid + s]);
        __syncthreads();
    }
    mx = red[0];
    __syncthreads();

    float sum = 0.0f;
#pragma unroll
    for (int i = 0; i < 8; i++) {
        v[i] = __expf(v[i] - mx);
        sum += v[i];
    }
    red[tid] = sum;
    __syncthreads();
#pragma unroll
    for (int s = 128; s > 0; s >>= 1) {
        if (tid < s) red[tid] += red[tid + s];
        __syncthreads();
    }
    const float inv = 1.0f / red[0];
#pragma unroll
    for (int i = 0; i < 8; i++)
        p[tid + i * 256] = v[i] * inv;
}

// -----------------------------------------------------------------------------
extern "C" void kernel_launch(void* const* d_in, const int* in_sizes, int n_in,
                              void* d_out, int out_size)
{
    const float* x     = (const float*)d_in[0];  // [2,2048,512]
    const float* W_sep = (const float*)d_in[1];  // [1536,512]
    const float* b_sep = (const float*)d_in[2];  // [1536]
    const float* W_mul = (const float*)d_in[3];  // [12288,1536]
    const float* b_mul = (const float*)d_in[4];  // [12288]
    const float* W_res = (const float*)d_in[5];  // [512,4096]
    const float* b_res = (const float*)d_in[6];  // [512]
    float* out = (float*)d_out;                  // [2,2048,512]

    float *h1, *h2, *sc, *ap;
    cudaGetSymbolAddress((void**)&h1, g_h1);
    cudaGetSymbolAddress((void**)&h2, g_h2);
    cudaGetSymbolAddress((void**)&sc, g_sc);
    cudaGetSymbolAddress((void**)&ap, g_ap);

    const int Bb = 2, S = 2048, D = 512, H = 8;
    const int M = Bb * S;  // 4096

    // GEMM1: h1[4096,1536] = x @ W_sep^T + b_sep
    sgemm_kernel<true><<<dim3(1536 / BN, M / BM, 1), 256>>>(
        x, W_sep, h1, b_sep, M, 1536, 512, 512, 512, 1536,
        1, 0, 0, 0, 0, 0, 0);

    // GEMM2: h2[4096,12288] = h1 @ W_mul^T + b_mul
    sgemm_kernel<true><<<dim3(12288 / BN, M / BM, 1), 256>>>(
        h1, W_mul, h2, b_mul, M, 12288, 1536, 1536, 1536, 12288,
        1, 0, 0, 0, 0, 0, 0);

    // QK^T batched over z = b*H + h: sc[z] = q_z @ k_z^T  (q,k views into h2)
    sgemm_kernel<true><<<dim3(2048 / BN, 2048 / BM, Bb * H), 256>>>(
        h2, h2 + 512, sc, nullptr, 2048, 2048, 512, 12288, 12288, 2048,
        H, (size_t)1536, (size_t)S * 12288,
           (size_t)1536, (size_t)S * 12288,
           (size_t)2048 * 2048, (size_t)H * 2048 * 2048);

    // softmax over keys, scale = 1/sqrt(512)
    softmax_rows<<<Bb * H * S, 256>>>(sc, 1.0f / sqrtf((float)D));

    // PV batched: ap[b, sq, h*512 + d] = sum_sk sc[z][sq][sk] * v[z][sk][d]
    sgemm_kernel<false><<<dim3(512 / BN, 2048 / BM, Bb * H), 256>>>(
        sc, h2 + 1024, ap, nullptr, 2048, 512, 2048, 2048, 12288, H * D,
        H, (size_t)2048 * 2048, (size_t)H * 2048 * 2048,
           (size_t)1536,        (size_t)S * 12288,
           (size_t)D,           (size_t)S * H * D);

    // GEMM3: out[4096,512] = ap @ W_res^T + b_res
    sgemm_kernel<true><<<dim3(512 / BN, M / BM, 1), 256>>>(
        ap, W_res, out, b_res, M, 512, 4096, 4096, 4096, 512,
        1, 0, 0, 0, 0, 0, 0);
}

// round 3
// speedup vs baseline: 2.5846x; 2.5846x over previous
#include <cuda_runtime.h>
#include <cuda_bf16.h>
#include <math.h>
#include <stdint.h>

// ===================== scratch (static device arrays) ========================
__device__ __nv_bfloat16 g_xh[4096UL * 512],    g_xl[4096UL * 512];
__device__ __nv_bfloat16 g_Wsh[1536UL * 512],   g_Wsl[1536UL * 512];
__device__ __nv_bfloat16 g_Wmh[12288UL * 1536], g_Wml[12288UL * 1536];
__device__ __nv_bfloat16 g_Wrh[512UL * 4096],   g_Wrl[512UL * 4096];
__device__ __nv_bfloat16 g_h1h[4096UL * 1536],  g_h1l[4096UL * 1536];
__device__ __nv_bfloat16 g_h2h[4096UL * 12288], g_h2l[4096UL * 12288];
__device__ float         g_sc [16UL * 2048 * 2048];
__device__ __nv_bfloat16 g_Ph [16UL * 2048 * 2048], g_Pl[16UL * 2048 * 2048];
__device__ __nv_bfloat16 g_Vth[16UL * 512 * 2048],  g_Vtl[16UL * 512 * 2048];
__device__ __nv_bfloat16 g_aph[4096UL * 4096],  g_apl[4096UL * 4096];

// ===================== helpers (base-target PTX only) ========================
__device__ __forceinline__ uint32_t smem_u32(const void* p) {
    uint32_t a;
    asm("{ .reg .u64 t; cvta.to.shared.u64 t, %1; cvt.u32.u64 %0, t; }"
        : "=r"(a) : "l"(p));
    return a;
}

__device__ __forceinline__ void cp16(uint32_t s, const void* g) {
    asm volatile("cp.async.cg.shared.global [%0], [%1], 16;"
                 :: "r"(s), "l"(g) : "memory");
}

__device__ __forceinline__ void ldsm4(uint32_t* r, uint32_t addr) {
    asm volatile("ldmatrix.sync.aligned.m8n8.x4.shared.b16 {%0,%1,%2,%3}, [%4];"
                 : "=r"(r[0]), "=r"(r[1]), "=r"(r[2]), "=r"(r[3]) : "r"(addr));
}

__device__ __forceinline__ void mma_bf16(float* c, const uint32_t* a, const uint32_t* b) {
    asm volatile(
        "mma.sync.aligned.m16n8k16.row.col.f32.bf16.bf16.f32 "
        "{%0,%1,%2,%3}, {%4,%5,%6,%7}, {%8,%9}, {%0,%1,%2,%3};"
        : "+f"(c[0]), "+f"(c[1]), "+f"(c[2]), "+f"(c[3])
        : "r"(a[0]), "r"(a[1]), "r"(a[2]), "r"(a[3]), "r"(b[0]), "r"(b[1]));
}

// swizzled smem offset for a [128][32] bf16 tile stored as 16B chunks
__device__ __forceinline__ uint32_t swz(int row, int chunk) {
    return (uint32_t)(row * 64 + ((chunk ^ ((row >> 1) & 3)) << 4));
}

// ===================== split-bf16 HMMA GEMM ==================================
// C = (Ah+Al) @ (Bh+Bl)^T  (dropping Al*Bl), fp32 accumulate.
// A: M x K (lda) bf16 K-major, B: N x K (ldb) bf16 K-major.
// Block tile 128x128x32, 256 threads, warp tile 32x64.
#define TILEB 8192            // one 128x32 bf16 tile
#define STAGEB (4 * TILEB)    // Ah, Al, Bh, Bl
#define SMEM_MM (2 * STAGEB)  // 65536

template <bool OUT_SPLIT>
__global__ __launch_bounds__(256, 1)
void gemm_mma(const __nv_bfloat16* __restrict__ Ah, const __nv_bfloat16* __restrict__ Al,
              const __nv_bfloat16* __restrict__ Bh, const __nv_bfloat16* __restrict__ Bl,
              float* __restrict__ Cf, __nv_bfloat16* __restrict__ Ch,
              __nv_bfloat16* __restrict__ Cl, const float* __restrict__ bias,
              int K, int lda, int ldb, int ldc, int NH,
              size_t sAh_, size_t sAb_, size_t sBh_, size_t sBb_,
              size_t sCh_, size_t sCb_)
{
    extern __shared__ char smem[];
    const uint32_t sbase = smem_u32(smem);
    const int tid = threadIdx.x, lane = tid & 31, w = tid >> 5;
    const int wm = w & 3, wn = w >> 2;

    const int z = blockIdx.z, hb = z % NH, bb = z / NH;
    const size_t offA = (size_t)hb * sAh_ + (size_t)bb * sAb_;
    const size_t offB = (size_t)hb * sBh_ + (size_t)bb * sBb_;
    const size_t offC = (size_t)hb * sCh_ + (size_t)bb * sCb_;

    const __nv_bfloat16* ah = Ah + offA + (size_t)(blockIdx.y * 128) * lda;
    const __nv_bfloat16* al = Al + offA + (size_t)(blockIdx.y * 128) * lda;
    const __nv_bfloat16* bh = Bh + offB + (size_t)(blockIdx.x * 128) * ldb;
    const __nv_bfloat16* bl = Bl + offB + (size_t)(blockIdx.x * 128) * ldb;

    float acc[2][8][4];
#pragma unroll
    for (int t = 0; t < 2; t++)
#pragma unroll
        for (int j = 0; j < 8; j++)
#pragma unroll
            for (int q = 0; q < 4; q++) acc[t][j][q] = 0.0f;

    // per-thread load slots: 2 chunks per tile
    const int ch0 = tid, ch1 = tid + 256;
    const int r0 = ch0 >> 2, c0 = ch0 & 3;
    const int r1 = ch1 >> 2, c1 = ch1 & 3;
    const uint32_t so0 = swz(r0, c0), so1 = swz(r1, c1);

    const int niter = K >> 5;

    auto issue = [&](int it) {
        const uint32_t sb = sbase + (uint32_t)(it & 1) * STAGEB;
        const int k0 = it << 5;
        const size_t ga0 = (size_t)r0 * lda + k0 + c0 * 8;
        const size_t ga1 = (size_t)r1 * lda + k0 + c1 * 8;
        const size_t gb0 = (size_t)r0 * ldb + k0 + c0 * 8;
        const size_t gb1 = (size_t)r1 * ldb + k0 + c1 * 8;
        cp16(sb + so0,              ah + ga0);
        cp16(sb + so1,              ah + ga1);
        cp16(sb + TILEB + so0,      al + ga0);
        cp16(sb + TILEB + so1,      al + ga1);
        cp16(sb + 2 * TILEB + so0,  bh + gb0);
        cp16(sb + 2 * TILEB + so1,  bh + gb1);
        cp16(sb + 3 * TILEB + so0,  bl + gb0);
        cp16(sb + 3 * TILEB + so1,  bl + gb1);
        asm volatile("cp.async.commit_group;" ::: "memory");
    };

    issue(0);

    for (int i = 0; i < niter; i++) {
        if (i + 1 < niter) {
            issue(i + 1);
            asm volatile("cp.async.wait_group 1;" ::: "memory");
        } else {
            asm volatile("cp.async.wait_group 0;" ::: "memory");
        }
        __syncthreads();

        const uint32_t sb = sbase + (uint32_t)(i & 1) * STAGEB;
#pragma unroll
        for (int k16 = 0; k16 < 2; k16++) {
            uint32_t a_hi[2][4], a_lo[2][4], bf[4][4];
            // A fragments (hi + lo)
            {
                const int rA = wm * 32 + (lane & 15);
                const int cA = k16 * 2 + (lane >> 4);
                const uint32_t oA0 = swz(rA, cA);
                const uint32_t oA1 = swz(rA + 16, cA);
                ldsm4(a_hi[0], sb + oA0);
                ldsm4(a_hi[1], sb + oA1);
                ldsm4(a_lo[0], sb + TILEB + oA0);
                ldsm4(a_lo[1], sb + TILEB + oA1);
            }
            // B hi fragments
            const int rBl = wn * 64 + (lane & 7) + ((lane >> 4) << 3);
            const int cB  = k16 * 2 + ((lane >> 3) & 1);
#pragma unroll
            for (int nt = 0; nt < 4; nt++)
                ldsm4(bf[nt], sb + 2 * TILEB + swz(rBl + nt * 16, cB));
            // hh + lh
#pragma unroll
            for (int t = 0; t < 2; t++)
#pragma unroll
                for (int nt = 0; nt < 4; nt++) {
                    mma_bf16(acc[t][nt * 2],     a_hi[t], &bf[nt][0]);
                    mma_bf16(acc[t][nt * 2 + 1], a_hi[t], &bf[nt][2]);
                    mma_bf16(acc[t][nt * 2],     a_lo[t], &bf[nt][0]);
                    mma_bf16(acc[t][nt * 2 + 1], a_lo[t], &bf[nt][2]);
                }
            // B lo fragments (reuse regs), hl
#pragma unroll
            for (int nt = 0; nt < 4; nt++)
                ldsm4(bf[nt], sb + 3 * TILEB + swz(rBl + nt * 16, cB));
#pragma unroll
            for (int t = 0; t < 2; t++)
#pragma unroll
                for (int nt = 0; nt < 4; nt++) {
                    mma_bf16(acc[t][nt * 2],     a_hi[t], &bf[nt][0]);
                    mma_bf16(acc[t][nt * 2 + 1], a_hi[t], &bf[nt][2]);
                }
        }
        __syncthreads();
    }

    // ---------------- epilogue ----------------
    const int row0 = blockIdx.y * 128 + wm * 32;
    const int col0 = blockIdx.x * 128 + wn * 64;
#pragma unroll
    for (int t = 0; t < 2; t++) {
#pragma unroll
        for (int j = 0; j < 8; j++) {
            const int r = row0 + t * 16 + (lane >> 2);
            const int c = col0 + j * 8 + (lane & 3) * 2;
            float b0 = 0.f, b1 = 0.f;
            if (bias) { b0 = __ldg(&bias[c]); b1 = __ldg(&bias[c + 1]); }
            const float v0 = acc[t][j][0] + b0, v1 = acc[t][j][1] + b1;
            const float v2 = acc[t][j][2] + b0, v3 = acc[t][j][3] + b1;
            const size_t o0 = offC + (size_t)r * ldc + c;
            const size_t o1 = offC + (size_t)(r + 8) * ldc + c;
            if (OUT_SPLIT) {
                __nv_bfloat162 hh, ll;
                hh.x = __float2bfloat16(v0);
                hh.y = __float2bfloat16(v1);
                ll.x = __float2bfloat16(v0 - __bfloat162float(hh.x));
                ll.y = __float2bfloat16(v1 - __bfloat162float(hh.y));
                *(__nv_bfloat162*)(Ch + o0) = hh;
                *(__nv_bfloat162*)(Cl + o0) = ll;
                hh.x = __float2bfloat16(v2);
                hh.y = __float2bfloat16(v3);
                ll.x = __float2bfloat16(v2 - __bfloat162float(hh.x));
                ll.y = __float2bfloat16(v3 - __bfloat162float(hh.y));
                *(__nv_bfloat162*)(Ch + o1) = hh;
                *(__nv_bfloat162*)(Cl + o1) = ll;
            } else {
                *(float2*)(Cf + o0) = make_float2(v0, v1);
                *(float2*)(Cf + o1) = make_float2(v2, v3);
            }
        }
    }
}

// ===================== aux kernels ===========================================
__global__ void split2(const float* __restrict__ x, __nv_bfloat16* __restrict__ h,
                       __nv_bfloat16* __restrict__ l, size_t n)
{
    size_t i = (size_t)blockIdx.x * blockDim.x + threadIdx.x;
    const size_t stride = (size_t)gridDim.x * blockDim.x;
    for (; i < n; i += stride) {
        float v = x[i];
        __nv_bfloat16 hi = __float2bfloat16(v);
        h[i] = hi;
        l[i] = __float2bfloat16(v - __bfloat162float(hi));
    }
}

__global__ void softmax_split(const float* __restrict__ sc,
                              __nv_bfloat16* __restrict__ ph,
                              __nv_bfloat16* __restrict__ pl, float scale)
{
    const int tid = threadIdx.x;
    const size_t base = (size_t)blockIdx.x * 2048;
    const float* p = sc + base;
    __shared__ float red[256];

    float v[8];
    float mx = -1e30f;
#pragma unroll
    for (int i = 0; i < 8; i++) {
        v[i] = p[tid + i * 256] * scale;
        mx = fmaxf(mx, v[i]);
    }
    red[tid] = mx;
    __syncthreads();
#pragma unroll
    for (int s = 128; s > 0; s >>= 1) {
        if (tid < s) red[tid] = fmaxf(red[tid], red[tid + s]);
        __syncthreads();
    }
    mx = red[0];
    __syncthreads();

    float sum = 0.0f;
#pragma unroll
    for (int i = 0; i < 8; i++) {
        v[i] = __expf(v[i] - mx);
        sum += v[i];
    }
    red[tid] = sum;
    __syncthreads();
#pragma unroll
    for (int s = 128; s > 0; s >>= 1) {
        if (tid < s) red[tid] += red[tid + s];
        __syncthreads();
    }
    const float inv = 1.0f / red[0];
#pragma unroll
    for (int i = 0; i < 8; i++) {
        float pv = v[i] * inv;
        __nv_bfloat16 hi = __float2bfloat16(pv);
        ph[base + tid + i * 256] = hi;
        pl[base + tid + i * 256] = __float2bfloat16(pv - __bfloat162float(hi));
    }
}

// V^T per (b,h): Vt[d][sk] = h2[(b,sk)][h*1536+1024+d]  (hi and lo)
__global__ void transpose_split_v(const __nv_bfloat16* __restrict__ h2h,
                                  const __nv_bfloat16* __restrict__ h2l,
                                  __nv_bfloat16* __restrict__ vth,
                                  __nv_bfloat16* __restrict__ vtl)
{
    __shared__ __nv_bfloat16 th[32][33], tl[32][33];
    const int z = blockIdx.z, b = z >> 3, h = z & 7;
    const int sk0 = blockIdx.x * 32, d0 = blockIdx.y * 32;
    const int tx = threadIdx.x, ty = threadIdx.y;  // 32 x 8
    const size_t srcbase = (size_t)b * 2048 * 12288 + h * 1536 + 1024;
#pragma unroll
    for (int j = 0; j < 4; j++) {
        int sk = sk0 + ty + j * 8;
        size_t s = srcbase + (size_t)sk * 12288 + d0 + tx;
        th[ty + j * 8][tx] = h2h[s];
        tl[ty + j * 8][tx] = h2l[s];
    }
    __syncthreads();
    const size_t dstbase = (size_t)(b * 8 + h) * 512 * 2048;
#pragma unroll
    for (int j = 0; j < 4; j++) {
        int d = d0 + ty + j * 8;
        size_t o = dstbase + (size_t)d * 2048 + sk0 + tx;
        vth[o] = th[tx][ty + j * 8];
        vtl[o] = tl[tx][ty + j * 8];
    }
}

// =============================================================================
extern "C" void kernel_launch(void* const* d_in, const int* in_sizes, int n_in,
                              void* d_out, int out_size)
{
    const float* x     = (const float*)d_in[0];
    const float* W_sep = (const float*)d_in[1];
    const float* b_sep = (const float*)d_in[2];
    const float* W_mul = (const float*)d_in[3];
    const float* b_mul = (const float*)d_in[4];
    const float* W_res = (const float*)d_in[5];
    const float* b_res = (const float*)d_in[6];
    float* out = (float*)d_out;

    __nv_bfloat16 *xh, *xl, *Wsh, *Wsl, *Wmh, *Wml, *Wrh, *Wrl;
    __nv_bfloat16 *h1h, *h1l, *h2h, *h2l, *Ph, *Pl, *Vth, *Vtl, *aph, *apl;
    float* sc;
    cudaGetSymbolAddress((void**)&xh,  g_xh);  cudaGetSymbolAddress((void**)&xl,  g_xl);
    cudaGetSymbolAddress((void**)&Wsh, g_Wsh); cudaGetSymbolAddress((void**)&Wsl, g_Wsl);
    cudaGetSymbolAddress((void**)&Wmh, g_Wmh); cudaGetSymbolAddress((void**)&Wml, g_Wml);
    cudaGetSymbolAddress((void**)&Wrh, g_Wrh); cudaGetSymbolAddress((void**)&Wrl, g_Wrl);
    cudaGetSymbolAddress((void**)&h1h, g_h1h); cudaGetSymbolAddress((void**)&h1l, g_h1l);
    cudaGetSymbolAddress((void**)&h2h, g_h2h); cudaGetSymbolAddress((void**)&h2l, g_h2l);
    cudaGetSymbolAddress((void**)&Ph,  g_Ph);  cudaGetSymbolAddress((void**)&Pl,  g_Pl);
    cudaGetSymbolAddress((void**)&Vth, g_Vth); cudaGetSymbolAddress((void**)&Vtl, g_Vtl);
    cudaGetSymbolAddress((void**)&aph, g_aph); cudaGetSymbolAddress((void**)&apl, g_apl);
    cudaGetSymbolAddress((void**)&sc,  g_sc);

    cudaFuncSetAttribute(gemm_mma<true>,  cudaFuncAttributeMaxDynamicSharedMemorySize, SMEM_MM);
    cudaFuncSetAttribute(gemm_mma<false>, cudaFuncAttributeMaxDynamicSharedMemorySize, SMEM_MM);

    const size_t S = 2048, D = 512, H = 8;

    // split inputs & weights into bf16 hi/lo
    split2<<<1024, 256>>>(x,     xh,  xl,  4096UL * 512);
    split2<<<1024, 256>>>(W_sep, Wsh, Wsl, 1536UL * 512);
    split2<<<2048, 256>>>(W_mul, Wmh, Wml, 12288UL * 1536);
    split2<<<1024, 256>>>(W_res, Wrh, Wrl, 512UL * 4096);

    // GEMM1: h1 = x @ W_sep^T + b_sep   [4096 x 1536], K=512
    gemm_mma<true><<<dim3(12, 32, 1), 256, SMEM_MM>>>(
        xh, xl, Wsh, Wsl, nullptr, h1h, h1l, b_sep,
        512, 512, 512, 1536, 1, 0, 0, 0, 0, 0, 0);

    // GEMM2: h2 = h1 @ W_mul^T + b_mul  [4096 x 12288], K=1536
    gemm_mma<true><<<dim3(96, 32, 1), 256, SMEM_MM>>>(
        h1h, h1l, Wmh, Wml, nullptr, h2h, h2l, b_mul,
        1536, 1536, 1536, 12288, 1, 0, 0, 0, 0, 0, 0);

    // QK^T batched (z = b*8 + h): sc[z] = Q @ K^T  [2048 x 2048], K=512
    gemm_mma<false><<<dim3(16, 16, 16), 256, SMEM_MM>>>(
        h2h, h2l, h2h + 512, h2l + 512, sc, nullptr, nullptr, nullptr,
        512, 12288, 12288, 2048, 8,
        1536, S * 12288, 1536, S * 12288,
        S * S, H * S * S);

    // softmax(scale * sc) -> P hi/lo
    softmax_split<<<16 * 2048, 256>>>(sc, Ph, Pl, 1.0f / sqrtf(512.0f));

    // V^T split
    transpose_split_v<<<dim3(64, 16, 16), dim3(32, 8)>>>(h2h, h2l, Vth, Vtl);

    // PV batched: ap[b, sq, h*512+d] = P @ Vt^T  [2048 x 512], K=2048
    gemm_mma<true><<<dim3(4, 16, 16), 256, SMEM_MM>>>(
        Ph, Pl, Vth, Vtl, nullptr, aph, apl, nullptr,
        2048, 2048, 2048, 4096, 8,
        S * S, H * S * S, D * S, H * D * S,
        512, S * 4096);

    // GEMM3: out = ap @ W_res^T + b_res  [4096 x 512], K=4096
    gemm_mma<false><<<dim3(4, 32, 1), 256, SMEM_MM>>>(
        aph, apl, Wrh, Wrl, out, nullptr, nullptr, b_res,
        4096, 4096, 4096, 512, 1, 0, 0, 0, 0, 0, 0);
}

// round 4
// speedup vs baseline: 2.6255x; 1.0158x over previous
#include <cuda_runtime.h>
#include <cuda_bf16.h>
#include <math.h>
#include <stdint.h>

// ===================== scratch (static device arrays) ========================
__device__ __nv_bfloat16 g_xh[4096UL * 512],    g_xl[4096UL * 512];
__device__ __nv_bfloat16 g_Wsh[1536UL * 512],   g_Wsl[1536UL * 512];
__device__ __nv_bfloat16 g_Wmh[12288UL * 1536], g_Wml[12288UL * 1536];
__device__ __nv_bfloat16 g_Wrh[512UL * 4096],   g_Wrl[512UL * 4096];
__device__ __nv_bfloat16 g_h1h[4096UL * 1536],  g_h1l[4096UL * 1536];
__device__ __nv_bfloat16 g_h2h[4096UL * 12288], g_h2l[4096UL * 12288];
__device__ float         g_sc [16UL * 2048 * 2048];
__device__ __nv_bfloat16 g_Ph [16UL * 2048 * 2048], g_Pl[16UL * 2048 * 2048];
__device__ __nv_bfloat16 g_Vth[16UL * 512 * 2048],  g_Vtl[16UL * 512 * 2048];
__device__ __nv_bfloat16 g_aph[4096UL * 4096],  g_apl[4096UL * 4096];

// ===================== helpers (base-target PTX only) ========================
__device__ __forceinline__ uint32_t smem_u32(const void* p) {
    uint32_t a;
    asm("{ .reg .u64 t; cvta.to.shared.u64 t, %1; cvt.u32.u64 %0, t; }"
        : "=r"(a) : "l"(p));
    return a;
}

__device__ __forceinline__ void cp16(uint32_t s, const void* g) {
    asm volatile("cp.async.cg.shared.global [%0], [%1], 16;"
                 :: "r"(s), "l"(g) : "memory");
}

__device__ __forceinline__ void ldsm4(uint32_t* r, uint32_t addr) {
    asm volatile("ldmatrix.sync.aligned.m8n8.x4.shared.b16 {%0,%1,%2,%3}, [%4];"
                 : "=r"(r[0]), "=r"(r[1]), "=r"(r[2]), "=r"(r[3]) : "r"(addr));
}

__device__ __forceinline__ void mma_bf16(float* c, const uint32_t* a, const uint32_t* b) {
    asm volatile(
        "mma.sync.aligned.m16n8k16.row.col.f32.bf16.bf16.f32 "
        "{%0,%1,%2,%3}, {%4,%5,%6,%7}, {%8,%9}, {%0,%1,%2,%3};"
        : "+f"(c[0]), "+f"(c[1]), "+f"(c[2]), "+f"(c[3])
        : "r"(a[0]), "r"(a[1]), "r"(a[2]), "r"(a[3]), "r"(b[0]), "r"(b[1]));
}

// swizzled smem offset for a [128][32] bf16 tile stored as 16B chunks
__device__ __forceinline__ uint32_t swz(int row, int chunk) {
    return (uint32_t)(row * 64 + ((chunk ^ ((row >> 1) & 3)) << 4));
}

// ===================== split-bf16 HMMA GEMM ==================================
// C = (Ah+Al) @ (Bh+Bl)^T  (dropping Al*Bl), fp32 accumulate.
// A: M x K (lda) bf16 K-major, B: N x K (ldb) bf16 K-major.
// Block tile 128x128x32, 256 threads, warp tile 32x64, 3-stage cp.async.
#define TILEB 8192            // one 128x32 bf16 tile
#define STAGEB (4 * TILEB)    // Ah, Al, Bh, Bl
#define NSTAGE 3
#define SMEM_MM (NSTAGE * STAGEB)  // 98304

template <bool OUT_SPLIT>
__global__ __launch_bounds__(256, 1)
void gemm_mma(const __nv_bfloat16* __restrict__ Ah, const __nv_bfloat16* __restrict__ Al,
              const __nv_bfloat16* __restrict__ Bh, const __nv_bfloat16* __restrict__ Bl,
              float* __restrict__ Cf, __nv_bfloat16* __restrict__ Ch,
              __nv_bfloat16* __restrict__ Cl, const float* __restrict__ bias,
              int K, int lda, int ldb, int ldc, int NH,
              size_t sAh_, size_t sAb_, size_t sBh_, size_t sBb_,
              size_t sCh_, size_t sCb_)
{
    extern __shared__ char smem[];
    const uint32_t sbase = smem_u32(smem);
    const int tid = threadIdx.x, lane = tid & 31, w = tid >> 5;
    const int wm = w & 3, wn = w >> 2;

    const int z = blockIdx.z, hb = z % NH, bb = z / NH;
    const size_t offA = (size_t)hb * sAh_ + (size_t)bb * sAb_;
    const size_t offB = (size_t)hb * sBh_ + (size_t)bb * sBb_;
    const size_t offC = (size_t)hb * sCh_ + (size_t)bb * sCb_;

    const __nv_bfloat16* ah = Ah + offA + (size_t)(blockIdx.y * 128) * lda;
    const __nv_bfloat16* al = Al + offA + (size_t)(blockIdx.y * 128) * lda;
    const __nv_bfloat16* bh = Bh + offB + (size_t)(blockIdx.x * 128) * ldb;
    const __nv_bfloat16* bl = Bl + offB + (size_t)(blockIdx.x * 128) * ldb;

    float acc[2][8][4];
#pragma unroll
    for (int t = 0; t < 2; t++)
#pragma unroll
        for (int j = 0; j < 8; j++)
#pragma unroll
            for (int q = 0; q < 4; q++) acc[t][j][q] = 0.0f;

    // per-thread load slots: 2 chunks per tile (512 chunks of 16B per tile)
    const int r0 = tid >> 2,         c0 = tid & 3;
    const int r1 = (tid + 256) >> 2, c1 = tid & 3;
    const uint32_t so0 = swz(r0, c0), so1 = swz(r1, c1);

    const int niter = K >> 5;

    auto issue = [&](int it) {
        const uint32_t sb = sbase + (uint32_t)(it % NSTAGE) * STAGEB;
        const int k0 = it << 5;
        const size_t ga0 = (size_t)r0 * lda + k0 + c0 * 8;
        const size_t ga1 = (size_t)r1 * lda + k0 + c1 * 8;
        const size_t gb0 = (size_t)r0 * ldb + k0 + c0 * 8;
        const size_t gb1 = (size_t)r1 * ldb + k0 + c1 * 8;
        cp16(sb + so0,              ah + ga0);
        cp16(sb + so1,              ah + ga1);
        cp16(sb + TILEB + so0,      al + ga0);
        cp16(sb + TILEB + so1,      al + ga1);
        cp16(sb + 2 * TILEB + so0,  bh + gb0);
        cp16(sb + 2 * TILEB + so1,  bh + gb1);
        cp16(sb + 3 * TILEB + so0,  bl + gb0);
        cp16(sb + 3 * TILEB + so1,  bl + gb1);
        asm volatile("cp.async.commit_group;" ::: "memory");
    };

    issue(0);
    if (niter > 1) issue(1);

    for (int i = 0; i < niter; i++) {
        if (i + 1 < niter)
            asm volatile("cp.async.wait_group 1;" ::: "memory");
        else
            asm volatile("cp.async.wait_group 0;" ::: "memory");
        __syncthreads();
        if (i + 2 < niter) issue(i + 2);  // writes buf (i-1)%3, freed by the barrier above

        const uint32_t sb = sbase + (uint32_t)(i % NSTAGE) * STAGEB;
#pragma unroll
        for (int k16 = 0; k16 < 2; k16++) {
            uint32_t a_hi[2][4], a_lo[2][4], b_hi[4][4], b_lo[4][4];
            const int rA = wm * 32 + (lane & 15);
            const int cA = k16 * 2 + (lane >> 4);
            const uint32_t oA0 = swz(rA, cA);
            const uint32_t oA1 = swz(rA + 16, cA);
            ldsm4(a_hi[0], sb + oA0);
            ldsm4(a_hi[1], sb + oA1);
            ldsm4(a_lo[0], sb + TILEB + oA0);
            ldsm4(a_lo[1], sb + TILEB + oA1);
            const int rB = wn * 64 + (lane & 7) + ((lane >> 4) << 3);
            const int cB = k16 * 2 + ((lane >> 3) & 1);
#pragma unroll
            for (int nt = 0; nt < 4; nt++) {
                const uint32_t oB = swz(rB + nt * 16, cB);
                ldsm4(b_hi[nt], sb + 2 * TILEB + oB);
                ldsm4(b_lo[nt], sb + 3 * TILEB + oB);
            }
            // product-major ordering: 16 independent MMAs between reuses of any acc
#pragma unroll
            for (int t = 0; t < 2; t++)
#pragma unroll
                for (int nt = 0; nt < 4; nt++) {
                    mma_bf16(acc[t][nt * 2],     a_hi[t], &b_hi[nt][0]);
                    mma_bf16(acc[t][nt * 2 + 1], a_hi[t], &b_hi[nt][2]);
                }
#pragma unroll
            for (int t = 0; t < 2; t++)
#pragma unroll
                for (int nt = 0; nt < 4; nt++) {
                    mma_bf16(acc[t][nt * 2],     a_lo[t], &b_hi[nt][0]);
                    mma_bf16(acc[t][nt * 2 + 1], a_lo[t], &b_hi[nt][2]);
                }
#pragma unroll
            for (int t = 0; t < 2; t++)
#pragma unroll
                for (int nt = 0; nt < 4; nt++) {
                    mma_bf16(acc[t][nt * 2],     a_hi[t], &b_lo[nt][0]);
                    mma_bf16(acc[t][nt * 2 + 1], a_hi[t], &b_lo[nt][2]);
                }
        }
        // no trailing barrier: next iteration's issue targets a buffer
        // protected by the barrier at the top of that iteration
    }

    // ---------------- epilogue ----------------
    const int row0 = blockIdx.y * 128 + wm * 32;
    const int col0 = blockIdx.x * 128 + wn * 64;
#pragma unroll
    for (int t = 0; t < 2; t++) {
#pragma unroll
        for (int j = 0; j < 8; j++) {
            const int r = row0 + t * 16 + (lane >> 2);
            const int c = col0 + j * 8 + (lane & 3) * 2;
            float b0 = 0.f, b1 = 0.f;
            if (bias) { b0 = __ldg(&bias[c]); b1 = __ldg(&bias[c + 1]); }
            const float v0 = acc[t][j][0] + b0, v1 = acc[t][j][1] + b1;
            const float v2 = acc[t][j][2] + b0, v3 = acc[t][j][3] + b1;
            const size_t o0 = offC + (size_t)r * ldc + c;
            const size_t o1 = offC + (size_t)(r + 8) * ldc + c;
            if (OUT_SPLIT) {
                __nv_bfloat162 hh, ll;
                hh.x = __float2bfloat16(v0);
                hh.y = __float2bfloat16(v1);
                ll.x = __float2bfloat16(v0 - __bfloat162float(hh.x));
                ll.y = __float2bfloat16(v1 - __bfloat162float(hh.y));
                *(__nv_bfloat162*)(Ch + o0) = hh;
                *(__nv_bfloat162*)(Cl + o0) = ll;
                hh.x = __float2bfloat16(v2);
                hh.y = __float2bfloat16(v3);
                ll.x = __float2bfloat16(v2 - __bfloat162float(hh.x));
                ll.y = __float2bfloat16(v3 - __bfloat162float(hh.y));
                *(__nv_bfloat162*)(Ch + o1) = hh;
                *(__nv_bfloat162*)(Cl + o1) = ll;
            } else {
                *(float2*)(Cf + o0) = make_float2(v0, v1);
                *(float2*)(Cf + o1) = make_float2(v2, v3);
            }
        }
    }
}

// ===================== aux kernels ===========================================
__global__ void split2(const float* __restrict__ x, __nv_bfloat16* __restrict__ h,
                       __nv_bfloat16* __restrict__ l, size_t n)
{
    size_t i = (size_t)blockIdx.x * blockDim.x + threadIdx.x;
    const size_t stride = (size_t)gridDim.x * blockDim.x;
    for (; i < n; i += stride) {
        float v = x[i];
        __nv_bfloat16 hi = __float2bfloat16(v);
        h[i] = hi;
        l[i] = __float2bfloat16(v - __bfloat162float(hi));
    }
}

__global__ void softmax_split(const float* __restrict__ sc,
                              __nv_bfloat16* __restrict__ ph,
                              __nv_bfloat16* __restrict__ pl, float scale)
{
    const int tid = threadIdx.x;
    const size_t base = (size_t)blockIdx.x * 2048;
    const float* p = sc + base;
    __shared__ float red[256];

    float v[8];
    float mx = -1e30f;
#pragma unroll
    for (int i = 0; i < 8; i++) {
        v[i] = p[tid + i * 256] * scale;
        mx = fmaxf(mx, v[i]);
    }
    red[tid] = mx;
    __syncthreads();
#pragma unroll
    for (int s = 128; s > 0; s >>= 1) {
        if (tid < s) red[tid] = fmaxf(red[tid], red[tid + s]);
        __syncthreads();
    }
    mx = red[0];
    __syncthreads();

    float sum = 0.0f;
#pragma unroll
    for (int i = 0; i < 8; i++) {
        v[i] = __expf(v[i] - mx);
        sum += v[i];
    }
    red[tid] = sum;
    __syncthreads();
#pragma unroll
    for (int s = 128; s > 0; s >>= 1) {
        if (tid < s) red[tid] += red[tid + s];
        __syncthreads();
    }
    const float inv = 1.0f / red[0];
#pragma unroll
    for (int i = 0; i < 8; i++) {
        float pv = v[i] * inv;
        __nv_bfloat16 hi = __float2bfloat16(pv);
        ph[base + tid + i * 256] = hi;
        pl[base + tid + i * 256] = __float2bfloat16(pv - __bfloat162float(hi));
    }
}

// V^T per (b,h): Vt[d][sk] = h2[(b,sk)][h*1536+1024+d]  (hi and lo)
__global__ void transpose_split_v(const __nv_bfloat16* __restrict__ h2h,
                                  const __nv_bfloat16* __restrict__ h2l,
                                  __nv_bfloat16* __restrict__ vth,
                                  __nv_bfloat16* __restrict__ vtl)
{
    __shared__ __nv_bfloat16 th[32][33], tl[32][33];
    const int z = blockIdx.z, b = z >> 3, h = z & 7;
    const int sk0 = blockIdx.x * 32, d0 = blockIdx.y * 32;
    const int tx = threadIdx.x, ty = threadIdx.y;  // 32 x 8
    const size_t srcbase = (size_t)b * 2048 * 12288 + h * 1536 + 1024;
#pragma unroll
    for (int j = 0; j < 4; j++) {
        int sk = sk0 + ty + j * 8;
        size_t s = srcbase + (size_t)sk * 12288 + d0 + tx;
        th[ty + j * 8][tx] = h2h[s];
        tl[ty + j * 8][tx] = h2l[s];
    }
    __syncthreads();
    const size_t dstbase = (size_t)(b * 8 + h) * 512 * 2048;
#pragma unroll
    for (int j = 0; j < 4; j++) {
        int d = d0 + ty + j * 8;
        size_t o = dstbase + (size_t)d * 2048 + sk0 + tx;
        vth[o] = th[tx][ty + j * 8];
        vtl[o] = tl[tx][ty + j * 8];
    }
}

// =============================================================================
extern "C" void kernel_launch(void* const* d_in, const int* in_sizes, int n_in,
                              void* d_out, int out_size)
{
    const float* x     = (const float*)d_in[0];
    const float* W_sep = (const float*)d_in[1];
    const float* b_sep = (const float*)d_in[2];
    const float* W_mul = (const float*)d_in[3];
    const float* b_mul = (const float*)d_in[4];
    const float* W_res = (const float*)d_in[5];
    const float* b_res = (const float*)d_in[6];
    float* out = (float*)d_out;

    __nv_bfloat16 *xh, *xl, *Wsh, *Wsl, *Wmh, *Wml, *Wrh, *Wrl;
    __nv_bfloat16 *h1h, *h1l, *h2h, *h2l, *Ph, *Pl, *Vth, *Vtl, *aph, *apl;
    float* sc;
    cudaGetSymbolAddress((void**)&xh,  g_xh);  cudaGetSymbolAddress((void**)&xl,  g_xl);
    cudaGetSymbolAddress((void**)&Wsh, g_Wsh); cudaGetSymbolAddress((void**)&Wsl, g_Wsl);
    cudaGetSymbolAddress((void**)&Wmh, g_Wmh); cudaGetSymbolAddress((void**)&Wml, g_Wml);
    cudaGetSymbolAddress((void**)&Wrh, g_Wrh); cudaGetSymbolAddress((void**)&Wrl, g_Wrl);
    cudaGetSymbolAddress((void**)&h1h, g_h1h); cudaGetSymbolAddress((void**)&h1l, g_h1l);
    cudaGetSymbolAddress((void**)&h2h, g_h2h); cudaGetSymbolAddress((void**)&h2l, g_h2l);
    cudaGetSymbolAddress((void**)&Ph,  g_Ph);  cudaGetSymbolAddress((void**)&Pl,  g_Pl);
    cudaGetSymbolAddress((void**)&Vth, g_Vth); cudaGetSymbolAddress((void**)&Vtl, g_Vtl);
    cudaGetSymbolAddress((void**)&aph, g_aph); cudaGetSymbolAddress((void**)&apl, g_apl);
    cudaGetSymbolAddress((void**)&sc,  g_sc);

    cudaFuncSetAttribute(gemm_mma<true>,  cudaFuncAttributeMaxDynamicSharedMemorySize, SMEM_MM);
    cudaFuncSetAttribute(gemm_mma<false>, cudaFuncAttributeMaxDynamicSharedMemorySize, SMEM_MM);

    const size_t S = 2048, D = 512, H = 8;

    // split inputs & weights into bf16 hi/lo
    split2<<<1024, 256>>>(x,     xh,  xl,  4096UL * 512);
    split2<<<1024, 256>>>(W_sep, Wsh, Wsl, 1536UL * 512);
    split2<<<2048, 256>>>(W_mul, Wmh, Wml, 12288UL * 1536);
    split2<<<1024, 256>>>(W_res, Wrh, Wrl, 512UL * 4096);

    // GEMM1: h1 = x @ W_sep^T + b_sep   [4096 x 1536], K=512
    gemm_mma<true><<<dim3(12, 32, 1), 256, SMEM_MM>>>(
        xh, xl, Wsh, Wsl, nullptr, h1h, h1l, b_sep,
        512, 512, 512, 1536, 1, 0, 0, 0, 0, 0, 0);

    // GEMM2: h2 = h1 @ W_mul^T + b_mul  [4096 x 12288], K=1536
    gemm_mma<true><<<dim3(96, 32, 1), 256, SMEM_MM>>>(
        h1h, h1l, Wmh, Wml, nullptr, h2h, h2l, b_mul,
        1536, 1536, 1536, 12288, 1, 0, 0, 0, 0, 0, 0);

    // QK^T batched (z = b*8 + h): sc[z] = Q @ K^T  [2048 x 2048], K=512
    gemm_mma<false><<<dim3(16, 16, 16), 256, SMEM_MM>>>(
        h2h, h2l, h2h + 512, h2l + 512, sc, nullptr, nullptr, nullptr,
        512, 12288, 12288, 2048, 8,
        1536, S * 12288, 1536, S * 12288,
        S * S, H * S * S);

    // softmax(scale * sc) -> P hi/lo
    softmax_split<<<16 * 2048, 256>>>(sc, Ph, Pl, 1.0f / sqrtf(512.0f));

    // V^T split
    transpose_split_v<<<dim3(64, 16, 16), dim3(32, 8)>>>(h2h, h2l, Vth, Vtl);

    // PV batched: ap[b, sq, h*512+d] = P @ Vt^T  [2048 x 512], K=2048
    gemm_mma<true><<<dim3(4, 16, 16), 256, SMEM_MM>>>(
        Ph, Pl, Vth, Vtl, nullptr, aph, apl, nullptr,
        2048, 2048, 2048, 4096, 8,
        S * S, H * S * S, D * S, H * D * S,
        512, S * 4096);

    // GEMM3: out = ap @ W_res^T + b_res  [4096 x 512], K=4096
    gemm_mma<false><<<dim3(4, 32, 1), 256, SMEM_MM>>>(
        aph, apl, Wrh, Wrl, out, nullptr, nullptr, b_res,
        4096, 4096, 4096, 512, 1, 0, 0, 0, 0, 0, 0);
}